// round 2
// baseline (speedup 1.0000x reference)
#include <cuda_runtime.h>

// y = s1 * FWHT( g * FWHT( s2 * x ) ) per token, D = 4096.
// All butterflies in registers (16 floats = 4 logical bits per thread).
// 4 XOR-swizzled shared-memory exchanges rotate which 4 bits live in regs:
//   L0(regs=bits0-3) -X1-> L1(bits4-7) -X2-> L2(bits8-11) [*g, bfly again]
//   -X3-> L3=L1(bits4-7) -X4-> L4=L0(bits0-3) [*s1, store]
// Each exchange: 16 conflict-free STS.32 + 4 conflict-free LDS.128.
// No shuffles anywhere.

#define DDIM 4096
#define TPC  4
#define B_(x,n) ((((unsigned)(x))>>(n))&1u)

__device__ __forceinline__ float softplus_f(float x) {
    return fmaxf(x, 0.0f) + log1pf(expf(-fabsf(x)));
}

// GF(2)-linear smem address maps (addr in floats, 12 bits).
// sig1: A0=i4 A1=i5 A2=i6^i0 A3=i7^i9 A4=i0^i8 A5=i1 A6=i2 A7=i3 A8..11=i8..11
__device__ __forceinline__ int sig1(int i) {
    return (int)( B_(i,4) | (B_(i,5)<<1) | ((B_(i,6)^B_(i,0))<<2) | ((B_(i,7)^B_(i,9))<<3)
                | ((B_(i,0)^B_(i,8))<<4) | (B_(i,1)<<5) | (B_(i,2)<<6) | (B_(i,3)<<7)
                | (B_(i,8)<<8) | (B_(i,9)<<9) | (B_(i,10)<<10) | (B_(i,11)<<11) );
}
// sig2: A0=i8 A1=i9 A2=i10^i1 A3=i11^i2 A4=i0^i4 A5=i1 A6=i2 A7=i3 A8..11=i4..7
__device__ __forceinline__ int sig2(int i) {
    return (int)( B_(i,8) | (B_(i,9)<<1) | ((B_(i,10)^B_(i,1))<<2) | ((B_(i,11)^B_(i,2))<<3)
                | ((B_(i,0)^B_(i,4))<<4) | (B_(i,1)<<5) | (B_(i,2)<<6) | (B_(i,3)<<7)
                | (B_(i,4)<<8) | (B_(i,5)<<9) | (B_(i,6)<<10) | (B_(i,7)<<11) );
}
// sig3: A0=i4 A1=i5 A2=i6^i8^i1 A3=i7^i9^i2 A4=i0^i3 A5=i1 A6=i2 A7=i3 A8..11=i8..11
__device__ __forceinline__ int sig3(int i) {
    return (int)( B_(i,4) | (B_(i,5)<<1) | ((B_(i,6)^B_(i,8)^B_(i,1))<<2)
                | ((B_(i,7)^B_(i,9)^B_(i,2))<<3)
                | ((B_(i,0)^B_(i,3))<<4) | (B_(i,1)<<5) | (B_(i,2)<<6) | (B_(i,3)<<7)
                | (B_(i,8)<<8) | (B_(i,9)<<9) | (B_(i,10)<<10) | (B_(i,11)<<11) );
}
// sig4: A0=i0 A1=i1 A2=i2^i4 A3=i3^i5^i8 A4=i6^i9 A5=i4 A6=i5 A7=i7 A8..11=i8..11
__device__ __forceinline__ int sig4(int i) {
    return (int)( B_(i,0) | (B_(i,1)<<1) | ((B_(i,2)^B_(i,4))<<2)
                | ((B_(i,3)^B_(i,5)^B_(i,8))<<3)
                | ((B_(i,6)^B_(i,9))<<4) | (B_(i,4)<<5) | (B_(i,5)<<6) | (B_(i,7)<<7)
                | (B_(i,8)<<8) | (B_(i,9)<<9) | (B_(i,10)<<10) | (B_(i,11)<<11) );
}

// In-register 4-bit FWHT over v[16] (reg index == the 4 logical bits).
__device__ __forceinline__ void bfly4(float v[16]) {
#pragma unroll
    for (int b = 1; b < 16; b <<= 1) {
#pragma unroll
        for (int r = 0; r < 16; r++) {
            if (!(r & b)) {
                float a = v[r], c = v[r | b];
                v[r]     = a + c;
                v[r | b] = a - c;
            }
        }
    }
}

__global__ void __launch_bounds__(256)
whvi_kernel(const float* __restrict__ x,
            const float* __restrict__ s1,
            const float* __restrict__ s2,
            const float* __restrict__ g_mu,
            const float* __restrict__ g_rho,
            const float* __restrict__ eps,
            float* __restrict__ out,
            int n_tokens)
{
    __shared__ float sh[DDIM];

    const int t = threadIdx.x;  // 256 threads

    // Thread-part logical indices per layout (reg bits zeroed).
    // L0: i{4..11} = t{0..7}
    const int iL0 = t << 4;
    // L1: t0=i8 t1=i9 t2=i0 t3=i1 t4=i2 t5=i3 t6=i10 t7=i11 (regs = i4..7)
    const int iL1 = ((t >> 2) & 7) | (((t >> 5) & 1) << 3)
                  | ((t & 3) << 8) | (((t >> 6) & 3) << 10);
    // L2: t0=i0 t1=i1 t2=i2 t3=i4 t4=i5 t5=i3 t6=i6 t7=i7 (regs = i8..11)
    const int iL2 = (t & 7) | (((t >> 5) & 1) << 3)
                  | (((t >> 3) & 3) << 4) | (((t >> 6) & 3) << 6);

    // Exchange bases (token-independent; σ are GF(2)-linear so
    // addr = base XOR σ(reg-offset), with the offset a compile-time const).
    const int wb1 = sig1(iL0), rb1 = sig1(iL1);
    const int wb2 = sig2(iL1), rb2 = sig2(iL2);
    const int wb3 = sig3(iL2), rb3 = sig3(iL1);
    const int wb4 = sig4(iL1), rb4 = sig4(iL0);

    // g_tilde in L2 layout (once per CTA; softplus is expensive).
    float gg[16];
#pragma unroll
    for (int r = 0; r < 16; r++) {
        const int i = iL2 | (r << 8);
        gg[r] = g_mu[i] + softplus_f(g_rho[i]) * eps[i];
    }

    const int tok0 = blockIdx.x * TPC;

    for (int it = 0; it < TPC; it++) {
        const int tok = tok0 + it;
        if (tok >= n_tokens) break;

        // ---- load x (float4, coalesced), multiply by s2 (L2-resident) ----
        float v[16];
        const float4* __restrict__ xr =
            (const float4*)(x + (size_t)tok * DDIM + iL0);
#pragma unroll
        for (int q = 0; q < 4; q++) {
            float4 xv  = xr[q];
            float4 s2v = *(const float4*)(s2 + iL0 + 4 * q);
            v[4*q+0] = xv.x * s2v.x;  v[4*q+1] = xv.y * s2v.y;
            v[4*q+2] = xv.z * s2v.z;  v[4*q+3] = xv.w * s2v.w;
        }

        bfly4(v);                         // FWHT1 bits 0-3

        // ---- X1: L0 -> L1 ----
        __syncthreads();
#pragma unroll
        for (int r = 0; r < 16; r++) sh[wb1 ^ sig1(r)] = v[r];
        __syncthreads();
#pragma unroll
        for (int q = 0; q < 4; q++) {
            float4 u = *(const float4*)(sh + (rb1 ^ sig1(q << 6)));
            v[4*q+0] = u.x; v[4*q+1] = u.y; v[4*q+2] = u.z; v[4*q+3] = u.w;
        }

        bfly4(v);                         // FWHT1 bits 4-7

        // ---- X2: L1 -> L2 ----
        __syncthreads();
#pragma unroll
        for (int r = 0; r < 16; r++) sh[wb2 ^ sig2(r << 4)] = v[r];
        __syncthreads();
#pragma unroll
        for (int q = 0; q < 4; q++) {
            float4 u = *(const float4*)(sh + (rb2 ^ sig2(q << 10)));
            v[4*q+0] = u.x; v[4*q+1] = u.y; v[4*q+2] = u.z; v[4*q+3] = u.w;
        }

        bfly4(v);                         // FWHT1 bits 8-11
#pragma unroll
        for (int r = 0; r < 16; r++) v[r] *= gg[r];   // *g_tilde
        bfly4(v);                         // FWHT2 bits 8-11

        // ---- X3: L2 -> L3(=L1) ----
        __syncthreads();
#pragma unroll
        for (int r = 0; r < 16; r++) sh[wb3 ^ sig3(r << 8)] = v[r];
        __syncthreads();
#pragma unroll
        for (int q = 0; q < 4; q++) {
            float4 u = *(const float4*)(sh + (rb3 ^ sig3(q << 6)));
            v[4*q+0] = u.x; v[4*q+1] = u.y; v[4*q+2] = u.z; v[4*q+3] = u.w;
        }

        bfly4(v);                         // FWHT2 bits 4-7

        // ---- X4: L3 -> L4(=L0) ----
        __syncthreads();
#pragma unroll
        for (int r = 0; r < 16; r++) sh[wb4 ^ sig4(r << 4)] = v[r];
        __syncthreads();
#pragma unroll
        for (int q = 0; q < 4; q++) {
            float4 u = *(const float4*)(sh + (rb4 ^ sig4(q << 2)));
            v[4*q+0] = u.x; v[4*q+1] = u.y; v[4*q+2] = u.z; v[4*q+3] = u.w;
        }

        bfly4(v);                         // FWHT2 bits 0-3

        // ---- *s1, store (float4, coalesced) ----
        float4* __restrict__ orow = (float4*)(out + (size_t)tok * DDIM + iL0);
#pragma unroll
        for (int q = 0; q < 4; q++) {
            float4 s1v = *(const float4*)(s1 + iL0 + 4 * q);
            orow[q] = make_float4(v[4*q+0] * s1v.x, v[4*q+1] * s1v.y,
                                  v[4*q+2] * s1v.z, v[4*q+3] * s1v.w);
        }
    }
}

extern "C" void kernel_launch(void* const* d_in, const int* in_sizes, int n_in,
                              void* d_out, int out_size)
{
    const float* x     = (const float*)d_in[0];
    const float* s1    = (const float*)d_in[1];
    const float* s2    = (const float*)d_in[2];
    const float* g_mu  = (const float*)d_in[3];
    const float* g_rho = (const float*)d_in[4];
    const float* eps   = (const float*)d_in[5];
    // d_in[6] = H, unused (FWHT computes it implicitly)

    float* out = (float*)d_out;
    const int n_tokens = in_sizes[0] / DDIM;
    const int grid = (n_tokens + TPC - 1) / TPC;

    whvi_kernel<<<grid, 256>>>(x, s1, s2, g_mu, g_rho, eps, out, n_tokens);
}

// round 4
// speedup vs baseline: 1.0056x; 1.0056x over previous
#include <cuda_runtime.h>

// y = s1 * FWHT( g * FWHT( s2 * x ) ) per token, D = 4096 = 2^12.
// 16 floats/thread = 4 logical index bits in registers; butterflies only in
// registers; 4 padded-stride smem exchanges rotate which bits are in regs.
//
// Layouts (i = 12-bit element index, t = thread 0..255, r = reg 0..15):
//   L0: i = (t<<4) | r                      regs = i0-3
//   L1: i = (t&15) | (r<<4) | ((t>>4)<<8)   regs = i4-7
//   L2: i = t | (r<<8)                      regs = i8-11
// Address maps on one 4352-float buffer:
//   addr17(i) = (i>>4)*17 + (i&15)   used by X1 (L0->L1) and X4 (L1->L0)
//   addr34(i) = (i>>5)*34 + (i&31)   used by X2 (L1->L2) and X3 (L2->L1)
// Every STS/LDS instruction is 32-bank bijective (verified per pattern):
//   addr17, lanes vary t0-4 with 17t  -> bijective (17 odd)
//   addr17, lanes vary i0-3 & i8      -> {c..c+15} U {c+16..c+31}  (272≡16)
//   addr34, lanes vary i0-3 & i8      -> same (34*8≡16, 16*(r&1) fixed)
//   addr34, lanes vary i0-4 (col)     -> banks = col, bijective

#define DDIM 4096
#define TPC  4

__device__ __forceinline__ float softplus_f(float x) {
    return fmaxf(x, 0.0f) + log1pf(expf(-fabsf(x)));
}

// In-register 4-bit FWHT over v[16] (reg index == logical bits).
__device__ __forceinline__ void bfly4(float v[16]) {
#pragma unroll
    for (int b = 1; b < 16; b <<= 1) {
#pragma unroll
        for (int r = 0; r < 16; r++) {
            if (!(r & b)) {
                float a = v[r], c = v[r | b];
                v[r]     = a + c;
                v[r | b] = a - c;
            }
        }
    }
}

__global__ void __launch_bounds__(256, 4)
whvi_kernel(const float* __restrict__ x,
            const float* __restrict__ s1,
            const float* __restrict__ s2,
            const float* __restrict__ g_mu,
            const float* __restrict__ g_rho,
            const float* __restrict__ eps,
            float* __restrict__ out,
            int n_tokens)
{
    __shared__ float sh[4352];     // max(256*17, 128*34) = 4352 floats
    __shared__ float gbuf[DDIM];   // g_tilde, linear (L2-indexed)

    const int t = threadIdx.x;     // 256 threads

    // Base addresses (all per-r offsets are compile-time immediates):
    //   X1w / X4r : addr = wA + r            (wA = 17*t)
    //   X1r / X4w : addr = rA + 17*r
    //   X2w / X3r : addr = rA + 34*(r>>1) + 16*(r&1)
    //   X2r / X3w : addr = rB + 272*r
    const int wA = 17 * t;
    const int rA = (t & 15) + 272 * (t >> 4);
    const int rB = (t & 31) + 34 * (t >> 5);

    // g_tilde once per CTA, linear layout: gbuf[i], i = t | (r<<8).
#pragma unroll
    for (int r = 0; r < 16; r++) {
        const int i = t + (r << 8);
        gbuf[i] = g_mu[i] + softplus_f(g_rho[i]) * eps[i];
    }
    // (ordered before first gbuf read by the X1/X2 barriers of token 0)

    const int tok0 = blockIdx.x * TPC;

    for (int it = 0; it < TPC; it++) {
        const int tok = tok0 + it;
        if (tok >= n_tokens) break;

        float v[16];
        // ---- load x (float4, coalesced), * s2 ---- (L0: i = t*16 + r)
        const float4* __restrict__ xr  = (const float4*)(x  + (size_t)tok * DDIM + (t << 4));
        const float4* __restrict__ s2r = (const float4*)(s2 + (t << 4));
#pragma unroll
        for (int q = 0; q < 4; q++) {
            float4 a = xr[q], b = s2r[q];
            v[4*q+0] = a.x * b.x;  v[4*q+1] = a.y * b.y;
            v[4*q+2] = a.z * b.z;  v[4*q+3] = a.w * b.w;
        }

        bfly4(v);                                    // FWHT1 bits 0-3

        // ---- X1: L0 -> L1 (addr17) ----
        __syncthreads();                             // WAR vs prev token X4 reads
#pragma unroll
        for (int r = 0; r < 16; r++) sh[wA + r] = v[r];
        __syncthreads();
#pragma unroll
        for (int r = 0; r < 16; r++) v[r] = sh[rA + 17 * r];

        bfly4(v);                                    // FWHT1 bits 4-7

        // ---- X2: L1 -> L2 (addr34) ----
        __syncthreads();
#pragma unroll
        for (int r = 0; r < 16; r++)
            sh[rA + 34 * (r >> 1) + 16 * (r & 1)] = v[r];
        __syncthreads();
#pragma unroll
        for (int r = 0; r < 16; r++) v[r] = sh[rB + 272 * r];

        bfly4(v);                                    // FWHT1 bits 8-11
#pragma unroll
        for (int r = 0; r < 16; r++)                 // * g_tilde (conflict-free)
            v[r] *= gbuf[t + (r << 8)];
        bfly4(v);                                    // FWHT2 bits 8-11

        // ---- X3: L2 -> L1 (addr34) ----
        __syncthreads();
#pragma unroll
        for (int r = 0; r < 16; r++) sh[rB + 272 * r] = v[r];
        __syncthreads();
#pragma unroll
        for (int r = 0; r < 16; r++)
            v[r] = sh[rA + 34 * (r >> 1) + 16 * (r & 1)];

        bfly4(v);                                    // FWHT2 bits 4-7

        // ---- X4: L1 -> L0 (addr17) ----
        __syncthreads();
#pragma unroll
        for (int r = 0; r < 16; r++) sh[rA + 17 * r] = v[r];
        __syncthreads();
#pragma unroll
        for (int r = 0; r < 16; r++) v[r] = sh[wA + r];

        bfly4(v);                                    // FWHT2 bits 0-3

        // ---- * s1, store (float4, coalesced) ----
        const float4* __restrict__ s1r = (const float4*)(s1 + (t << 4));
        float4* __restrict__ orow = (float4*)(out + (size_t)tok * DDIM + (t << 4));
#pragma unroll
        for (int q = 0; q < 4; q++) {
            float4 b = s1r[q];
            orow[q] = make_float4(v[4*q+0] * b.x, v[4*q+1] * b.y,
                                  v[4*q+2] * b.z, v[4*q+3] * b.w);
        }
    }
}

extern "C" void kernel_launch(void* const* d_in, const int* in_sizes, int n_in,
                              void* d_out, int out_size)
{
    const float* x     = (const float*)d_in[0];
    const float* s1    = (const float*)d_in[1];
    const float* s2    = (const float*)d_in[2];
    const float* g_mu  = (const float*)d_in[3];
    const float* g_rho = (const float*)d_in[4];
    const float* eps   = (const float*)d_in[5];
    // d_in[6] = H, unused (FWHT computes it implicitly)

    float* out = (float*)d_out;
    const int n_tokens = in_sizes[0] / DDIM;
    const int grid = (n_tokens + TPC - 1) / TPC;

    whvi_kernel<<<grid, 256>>>(x, s1, s2, g_mu, g_rho, eps, out, n_tokens);
}